// round 4
// baseline (speedup 1.0000x reference)
#include <cuda_runtime.h>
#include <cstdint>

#define NB   16
#define CIN  256
#define CR   64
#define HWSZ 2304
#define NJT  18            // 2304 / 128 column tiles
#define NIT  36            // 2304 / 64  row tiles

// Scratch (device globals: no allocation allowed)
__device__ float g_q[NB*CR*HWSZ];
__device__ float g_k[NB*CR*HWSZ];
__device__ float g_v[NB*CR*HWSZ];
__device__ float g_att[NB*CR*HWSZ];
__device__ float g_partial[NB*NJT];

// ---------------------------------------------------------------------------
// Kernel 1: QKV projection.  out[n,c,p] = sum_ci W[c,ci] * x[n,ci,p] + b[c]
// Grid: (18 j-tiles, 16 batches, 3 {q,k,v}); 256 threads; tile 64x128, BK=32.
// ---------------------------------------------------------------------------
__global__ __launch_bounds__(256) void qkv_kernel(
    const float* __restrict__ x,
    const float* __restrict__ Wq, const float* __restrict__ bq,
    const float* __restrict__ Wk, const float* __restrict__ bk,
    const float* __restrict__ Wv, const float* __restrict__ bv)
{
    __shared__ float sW[32*68];    // [k][c], padded stride 68
    __shared__ float sX[32*128];   // [k][j]

    const int tid = threadIdx.x;
    const int tx = tid & 15, ty = tid >> 4;
    const int n  = blockIdx.y;
    const int j0 = blockIdx.x * 128;
    const int which = blockIdx.z;

    const float* W = (which == 0) ? Wq : (which == 1) ? Wk : Wv;
    const float* b = (which == 0) ? bq : (which == 1) ? bk : bv;
    float* out = (which == 0) ? g_q : (which == 1) ? g_k : g_v;

    float acc[4][8];
    #pragma unroll
    for (int i = 0; i < 4; i++)
        #pragma unroll
        for (int j = 0; j < 8; j++) acc[i][j] = 0.f;

    for (int kk = 0; kk < CIN; kk += 32) {
        // W tile: 64 c x 32 k, transposed into sW[k][c]
        for (int t = tid; t < 64*32; t += 256) {
            int c = t >> 5, k = t & 31;
            sW[k*68 + c] = W[c*CIN + kk + k];
        }
        // X tile: 32 k x 128 j (float4)
        for (int t = tid; t < 32*32; t += 256) {
            int k = t >> 5, jf = t & 31;
            *(float4*)&sX[k*128 + jf*4] =
                *(const float4*)&x[((size_t)n*CIN + kk + k)*HWSZ + j0 + jf*4];
        }
        __syncthreads();

        #pragma unroll 8
        for (int k = 0; k < 32; k++) {
            float4 w4 = *(float4*)&sW[k*68 + ty*4];
            float4 xa = *(float4*)&sX[k*128 + tx*8];
            float4 xb = *(float4*)&sX[k*128 + tx*8 + 4];
            float wv[4] = {w4.x, w4.y, w4.z, w4.w};
            float xv[8] = {xa.x, xa.y, xa.z, xa.w, xb.x, xb.y, xb.z, xb.w};
            #pragma unroll
            for (int i = 0; i < 4; i++)
                #pragma unroll
                for (int j = 0; j < 8; j++)
                    acc[i][j] = fmaf(wv[i], xv[j], acc[i][j]);
        }
        __syncthreads();
    }

    #pragma unroll
    for (int cc = 0; cc < 4; cc++) {
        int c = ty*4 + cc;
        float bb = b[c];
        float4 r0 = make_float4(acc[cc][0]+bb, acc[cc][1]+bb, acc[cc][2]+bb, acc[cc][3]+bb);
        float4 r1 = make_float4(acc[cc][4]+bb, acc[cc][5]+bb, acc[cc][6]+bb, acc[cc][7]+bb);
        size_t base = ((size_t)n*CR + c)*HWSZ + j0 + tx*8;
        *(float4*)&out[base]     = r0;
        *(float4*)&out[base + 4] = r1;
    }
}

// ---------------------------------------------------------------------------
// Kernel 2: fused attention.  For a 128-column tile of Q:
//   loop 64-row tiles of K,V:  P = exp(K_tile^T Q_tile);  A += V_tile * P
// Also accumulates per-block sum of exp -> g_partial (deterministic).
// Grid: (18, 16); 256 threads; ~97 KB dynamic smem; 2 blocks/SM.
// ---------------------------------------------------------------------------
__global__ __launch_bounds__(256, 2) void attn_kernel()
{
    extern __shared__ float sm[];
    float* sQ  = sm;                 // 64 x 128
    float* sK  = sQ  + 64*128;       // 64 x 64
    float* sVt = sK  + 64*64;        // 64 x 68  (transposed, padded)
    float* sP  = sVt + 64*68;        // 64 x 128

    const int tid = threadIdx.x;
    const int tx = tid & 15, ty = tid >> 4;
    const int n  = blockIdx.y;
    const int j0 = blockIdx.x * 128;

    // Q tile: loaded once, reused for all 36 K/V tiles
    for (int t = tid; t < 64*32; t += 256) {
        int c = t >> 5, jf = t & 31;
        *(float4*)&sQ[c*128 + jf*4] =
            *(const float4*)&g_q[((size_t)n*CR + c)*HWSZ + j0 + jf*4];
    }

    float acc[4][8];
    #pragma unroll
    for (int i = 0; i < 4; i++)
        #pragma unroll
        for (int j = 0; j < 8; j++) acc[i][j] = 0.f;
    float lsum = 0.f;

    for (int it = 0; it < NIT; it++) {
        const int i0 = it * 64;
        // K tile [c][i]
        for (int t = tid; t < 64*16; t += 256) {
            int c = t >> 4, f = t & 15;
            *(float4*)&sK[c*64 + f*4] =
                *(const float4*)&g_k[((size_t)n*CR + c)*HWSZ + i0 + f*4];
        }
        // V tile transposed: sVt[i][c]
        for (int t = tid; t < 64*64; t += 256) {
            int c = t >> 6, i = t & 63;
            sVt[i*68 + c] = g_v[((size_t)n*CR + c)*HWSZ + i0 + i];
        }
        __syncthreads();

        // Phase 1: P[i,j] = sum_c K[c,i]*Q[c,j]
        float p[4][8];
        #pragma unroll
        for (int i = 0; i < 4; i++)
            #pragma unroll
            for (int j = 0; j < 8; j++) p[i][j] = 0.f;

        #pragma unroll 8
        for (int c = 0; c < 64; c++) {
            float4 k4 = *(float4*)&sK[c*64 + ty*4];
            float4 qa = *(float4*)&sQ[c*128 + tx*8];
            float4 qb = *(float4*)&sQ[c*128 + tx*8 + 4];
            float kv[4] = {k4.x, k4.y, k4.z, k4.w};
            float qv[8] = {qa.x, qa.y, qa.z, qa.w, qb.x, qb.y, qb.z, qb.w};
            #pragma unroll
            for (int i = 0; i < 4; i++)
                #pragma unroll
                for (int j = 0; j < 8; j++)
                    p[i][j] = fmaf(kv[i], qv[j], p[i][j]);
        }

        // exp + local sum + stage P to smem
        #pragma unroll
        for (int i = 0; i < 4; i++) {
            #pragma unroll
            for (int j = 0; j < 8; j++) {
                float e = __expf(p[i][j]);
                lsum += e;
                p[i][j] = e;
            }
            *(float4*)&sP[(ty*4+i)*128 + tx*8]     = make_float4(p[i][0], p[i][1], p[i][2], p[i][3]);
            *(float4*)&sP[(ty*4+i)*128 + tx*8 + 4] = make_float4(p[i][4], p[i][5], p[i][6], p[i][7]);
        }
        __syncthreads();

        // Phase 2: A[c,j] += sum_i V[c,i] * P[i,j]
        #pragma unroll 8
        for (int i = 0; i < 64; i++) {
            float4 v4 = *(float4*)&sVt[i*68 + ty*4];
            float4 pa = *(float4*)&sP[i*128 + tx*8];
            float4 pb = *(float4*)&sP[i*128 + tx*8 + 4];
            float vv[4] = {v4.x, v4.y, v4.z, v4.w};
            float pv[8] = {pa.x, pa.y, pa.z, pa.w, pb.x, pb.y, pb.z, pb.w};
            #pragma unroll
            for (int c = 0; c < 4; c++)
                #pragma unroll
                for (int j = 0; j < 8; j++)
                    acc[c][j] = fmaf(vv[c], pv[j], acc[c][j]);
        }
        __syncthreads();
    }

    // Write unnormalized A
    #pragma unroll
    for (int cc = 0; cc < 4; cc++) {
        int c = ty*4 + cc;
        size_t base = ((size_t)n*CR + c)*HWSZ + j0 + tx*8;
        *(float4*)&g_att[base]     = make_float4(acc[cc][0], acc[cc][1], acc[cc][2], acc[cc][3]);
        *(float4*)&g_att[base + 4] = make_float4(acc[cc][4], acc[cc][5], acc[cc][6], acc[cc][7]);
    }

    // Block-level sum of exp (deterministic; no atomics)
    #pragma unroll
    for (int off = 16; off > 0; off >>= 1)
        lsum += __shfl_xor_sync(0xFFFFFFFFu, lsum, off);
    if ((tid & 31) == 0) sK[tid >> 5] = lsum;   // sK reusable after last sync
    __syncthreads();
    if (tid == 0) {
        float s = 0.f;
        #pragma unroll
        for (int w = 0; w < 8; w++) s += sK[w];
        g_partial[n*NJT + blockIdx.x] = s;
    }
}

// ---------------------------------------------------------------------------
// Kernel 3: out[n,o,p] = g * (Watt[o,:] @ (A[:,p]/S[n]) + batt[o]) + g
// Grid: (36 j-tiles of 64, 4 o-tiles of 64, 16 batches); 256 threads.
// ---------------------------------------------------------------------------
__global__ __launch_bounds__(256) void out_kernel(
    const float* __restrict__ gco,
    const float* __restrict__ Watt, const float* __restrict__ batt,
    float* __restrict__ out)
{
    __shared__ float sW[64*68];   // [k][o], padded
    __shared__ float sA[64*68];   // [k][j], padded
    __shared__ float sS;

    const int tid = threadIdx.x;
    const int tx = tid & 15, ty = tid >> 4;
    const int n  = blockIdx.z;
    const int o0 = blockIdx.y * 64;
    const int j0 = blockIdx.x * 64;

    if (tid == 0) {
        float s = 0.f;
        #pragma unroll
        for (int t = 0; t < NJT; t++) s += g_partial[n*NJT + t];
        sS = s;
    }
    for (int t = tid; t < 64*64; t += 256) {
        int o = t >> 6, k = t & 63;
        sW[k*68 + o] = Watt[(size_t)(o0 + o)*CR + k];
    }
    for (int t = tid; t < 64*64; t += 256) {
        int c = t >> 6, j = t & 63;
        sA[c*68 + j] = g_att[((size_t)n*CR + c)*HWSZ + j0 + j];
    }
    __syncthreads();

    float acc[4][4];
    #pragma unroll
    for (int i = 0; i < 4; i++)
        #pragma unroll
        for (int j = 0; j < 4; j++) acc[i][j] = 0.f;

    #pragma unroll 8
    for (int k = 0; k < 64; k++) {
        float4 w4 = *(float4*)&sW[k*68 + ty*4];
        float4 a4 = *(float4*)&sA[k*68 + tx*4];
        float wv[4] = {w4.x, w4.y, w4.z, w4.w};
        float av[4] = {a4.x, a4.y, a4.z, a4.w};
        #pragma unroll
        for (int i = 0; i < 4; i++)
            #pragma unroll
            for (int j = 0; j < 4; j++)
                acc[i][j] = fmaf(wv[i], av[j], acc[i][j]);
    }

    const float invS = 1.f / sS;
    #pragma unroll
    for (int oi = 0; oi < 4; oi++) {
        int o = o0 + ty*4 + oi;
        float bias = batt[o];
        size_t base = ((size_t)n*CIN + o)*HWSZ + j0 + tx*4;
        float4 g = *(const float4*)&gco[base];
        float4 r;
        r.x = g.x * (fmaf(acc[oi][0], invS, bias) + 1.f);
        r.y = g.y * (fmaf(acc[oi][1], invS, bias) + 1.f);
        r.z = g.z * (fmaf(acc[oi][2], invS, bias) + 1.f);
        r.w = g.w * (fmaf(acc[oi][3], invS, bias) + 1.f);
        *(float4*)&out[base] = r;
    }
}

// ---------------------------------------------------------------------------
extern "C" void kernel_launch(void* const* d_in, const int* in_sizes, int n_in,
                              void* d_out, int out_size)
{
    const float* x    = (const float*)d_in[0];   // feature_maps [16,256,48,48]
    const float* gco  = (const float*)d_in[1];   // global_channel_output
    const float* Wq   = (const float*)d_in[2];
    const float* bq   = (const float*)d_in[3];
    const float* Wk   = (const float*)d_in[4];
    const float* bk   = (const float*)d_in[5];
    const float* Wv   = (const float*)d_in[6];
    const float* bv   = (const float*)d_in[7];
    const float* Watt = (const float*)d_in[8];
    const float* batt = (const float*)d_in[9];
    float* out = (float*)d_out;

    const int smem2 = (64*128 + 64*64 + 64*68 + 64*128) * 4;  // 99328 B
    cudaFuncSetAttribute(attn_kernel, cudaFuncAttributeMaxDynamicSharedMemorySize, smem2);

    qkv_kernel<<<dim3(NJT, NB, 3), 256>>>(x, Wq, bq, Wk, bk, Wv, bv);
    attn_kernel<<<dim3(NJT, NB), 256, smem2>>>();
    out_kernel<<<dim3(NIT, 4, NB), 256>>>(gco, Watt, batt, out);
}

// round 11
// speedup vs baseline: 2.6177x; 2.6177x over previous
#include <cuda_runtime.h>
#include <cuda_fp16.h>
#include <cstdint>

#define NB   16
#define CIN  256
#define CR   64
#define HWSZ 2304
#define NJT  18            // 2304 / 128 j tiles
#define NIT  36            // out kernel j tiles of 64
#define NITA 18            // attn i tiles of 128

#define PSCALE  4.8828125e-4f   // 2^-11 applied to exp before fp16
#define PSCALEI 2048.0f         // inverse, applied when writing att

// ---------------- scratch (device globals; no allocation allowed) ----------
__device__ __half g_qTh[NB*HWSZ*CR], g_qTl[NB*HWSZ*CR];   // [n][pos][c]
__device__ __half g_kTh[NB*HWSZ*CR], g_kTl[NB*HWSZ*CR];   // [n][pos][c]
__device__ __half g_vh [NB*CR*HWSZ], g_vl [NB*CR*HWSZ];   // [n][c][pos]
__device__ float  g_att[NB*HWSZ*CR];                       // [n][pos][c] = att^T
__device__ float  g_partial[NB*NJT];

// ---------------- helpers (sm_80-level PTX only; no 'a' features) ----------
__device__ __forceinline__ uint32_t smem_u32(const void* p) {
    uint32_t a;
    asm("{ .reg .u64 t; cvta.to.shared.u64 t, %1; cvt.u32.u64 %0, t; }" : "=r"(a) : "l"(p));
    return a;
}
__device__ __forceinline__ void mma16816(float* d, const uint32_t* a, const uint32_t* b) {
    asm volatile("mma.sync.aligned.m16n8k16.row.col.f32.f16.f16.f32 "
        "{%0,%1,%2,%3}, {%4,%5,%6,%7}, {%8,%9}, {%0,%1,%2,%3};"
        : "+f"(d[0]), "+f"(d[1]), "+f"(d[2]), "+f"(d[3])
        : "r"(a[0]), "r"(a[1]), "r"(a[2]), "r"(a[3]), "r"(b[0]), "r"(b[1]));
}
__device__ __forceinline__ void ldsm_x4(uint32_t* r, uint32_t addr) {
    asm volatile("ldmatrix.sync.aligned.m8n8.x4.shared.b16 {%0,%1,%2,%3}, [%4];"
        : "=r"(r[0]), "=r"(r[1]), "=r"(r[2]), "=r"(r[3]) : "r"(addr));
}
__device__ __forceinline__ void ldsm_x2(uint32_t* r, uint32_t addr) {
    asm volatile("ldmatrix.sync.aligned.m8n8.x2.shared.b16 {%0,%1}, [%2];"
        : "=r"(r[0]), "=r"(r[1]) : "r"(addr));
}
__device__ __forceinline__ void cpa16(uint32_t dst, const void* src) {
    asm volatile("cp.async.cg.shared.global [%0], [%1], 16;" :: "r"(dst), "l"(src));
}
#define CPA_COMMIT() asm volatile("cp.async.commit_group;" ::: "memory")
#define CPA_WAIT0()  asm volatile("cp.async.wait_group 0;" ::: "memory")
#define CPA_WAIT1()  asm volatile("cp.async.wait_group 1;" ::: "memory")
// pack two f32 -> f16x2 (lo = first arg)
__device__ __forceinline__ uint32_t pack_h2(float lo, float hi) {
    uint32_t r;
    asm("cvt.rn.f16x2.f32 %0, %1, %2;" : "=r"(r) : "f"(hi), "f"(lo));
    return r;
}

// ---------------------------------------------------------------------------
// Kernel 1: QKV projection (fp32 GEMM) -> fp16 high/low split outputs.
// q,k stored transposed [n][pos][c]; v stored [n][c][pos].
// ---------------------------------------------------------------------------
__global__ __launch_bounds__(256) void qkv_kernel(
    const float* __restrict__ x,
    const float* __restrict__ Wq, const float* __restrict__ bq,
    const float* __restrict__ Wk, const float* __restrict__ bk,
    const float* __restrict__ Wv, const float* __restrict__ bv)
{
    __shared__ float sW[32*68];
    __shared__ float sX[32*128];

    const int tid = threadIdx.x;
    const int tx = tid & 15, ty = tid >> 4;
    const int n  = blockIdx.y;
    const int j0 = blockIdx.x * 128;
    const int which = blockIdx.z;

    const float* W = (which == 0) ? Wq : (which == 1) ? Wk : Wv;
    const float* b = (which == 0) ? bq : (which == 1) ? bk : bv;

    float acc[4][8];
    #pragma unroll
    for (int i = 0; i < 4; i++)
        #pragma unroll
        for (int j = 0; j < 8; j++) acc[i][j] = 0.f;

    for (int kk = 0; kk < CIN; kk += 32) {
        for (int t = tid; t < 64*32; t += 256) {
            int c = t >> 5, k = t & 31;
            sW[k*68 + c] = W[c*CIN + kk + k];
        }
        for (int t = tid; t < 32*32; t += 256) {
            int k = t >> 5, jf = t & 31;
            *(float4*)&sX[k*128 + jf*4] =
                *(const float4*)&x[((size_t)n*CIN + kk + k)*HWSZ + j0 + jf*4];
        }
        __syncthreads();

        #pragma unroll 8
        for (int k = 0; k < 32; k++) {
            float4 w4 = *(float4*)&sW[k*68 + ty*4];
            float4 xa = *(float4*)&sX[k*128 + tx*8];
            float4 xb = *(float4*)&sX[k*128 + tx*8 + 4];
            float wv[4] = {w4.x, w4.y, w4.z, w4.w};
            float xv[8] = {xa.x, xa.y, xa.z, xa.w, xb.x, xb.y, xb.z, xb.w};
            #pragma unroll
            for (int i = 0; i < 4; i++)
                #pragma unroll
                for (int j = 0; j < 8; j++)
                    acc[i][j] = fmaf(wv[i], xv[j], acc[i][j]);
        }
        __syncthreads();
    }

    if (which < 2) {
        __half* oh = (which == 0) ? g_qTh : g_kTh;
        __half* ol = (which == 0) ? g_qTl : g_kTl;
        float4 b4 = *(const float4*)&b[ty*4];
        float bv4[4] = {b4.x, b4.y, b4.z, b4.w};
        #pragma unroll
        for (int jj = 0; jj < 8; jj++) {
            union { __half h[4]; uint2 u; } H, L;
            #pragma unroll
            for (int cc = 0; cc < 4; cc++) {
                float v = acc[cc][jj] + bv4[cc];
                __half hi = __float2half_rn(v);
                H.h[cc] = hi;
                L.h[cc] = __float2half_rn(v - __half2float(hi));
            }
            size_t row = (size_t)n*HWSZ + j0 + tx*8 + jj;
            *(uint2*)&oh[row*CR + ty*4] = H.u;
            *(uint2*)&ol[row*CR + ty*4] = L.u;
        }
    } else {
        #pragma unroll
        for (int cc = 0; cc < 4; cc++) {
            int c = ty*4 + cc;
            float bb = b[c];
            union { __half h[8]; uint4 u; } H, L;
            #pragma unroll
            for (int jj = 0; jj < 8; jj++) {
                float v = acc[cc][jj] + bb;
                __half hi = __float2half_rn(v);
                H.h[jj] = hi;
                L.h[jj] = __float2half_rn(v - __half2float(hi));
            }
            size_t base = ((size_t)n*CR + c)*HWSZ + j0 + tx*8;
            *(uint4*)&g_vh[base] = H.u;
            *(uint4*)&g_vl[base] = L.u;
        }
    }
}

// ---------------------------------------------------------------------------
// Kernel 2: FA2-style HMMA attention (fp16 splits, fp32 accum).
// Per CTA: (n, 128 j rows). 8 warps, each owns 16 j rows.
//   MMA1: P[j,i] = Q^T K  (3-split fp16)  -> exp (fp32) -> fp16 (x 2^-11)
//   MMA2: attT[j,c] += P V^T  (V 2-split, P A-frag direct from registers)
// Double-buffered cp.async K/V tiles. Q fragments persistent in registers.
// ---------------------------------------------------------------------------
#define QSTRIDE 144    // bytes per [pos][64c] row (128B + 16B pad)
#define VSTRIDE 272    // bytes per [c][128i] row (256B + 16B pad)
#define SM_RED  0
#define SM_QH   128
#define SM_QL   (SM_QH + 128*QSTRIDE)                 // 18560
#define SM_KH   (SM_QL + 128*QSTRIDE)                 // 36992, 2 bufs
#define SM_KL   (SM_KH + 2*128*QSTRIDE)               // 73856, 2 bufs
#define SM_VH   (SM_KL + 2*128*QSTRIDE)               // 110720, 2 bufs
#define SM_VL   (SM_VH + 2*64*VSTRIDE)                // 145536, 2 bufs
#define SM_TOT  (SM_VL + 2*64*VSTRIDE)                // 180352

__global__ __launch_bounds__(256, 1) void attn_kernel()
{
    extern __shared__ char smem[];
    const uint32_t sb = smem_u32(smem);
    const int tid = threadIdx.x, wid = tid >> 5, lane = tid & 31;
    const int n = blockIdx.y, j0 = blockIdx.x * 128;

    // ---- stage Q (h,l) ----
    {
        const char* qh = (const char*)(g_qTh + ((size_t)n*HWSZ + j0)*CR);
        const char* ql = (const char*)(g_qTl + ((size_t)n*HWSZ + j0)*CR);
        for (int t = tid; t < 1024; t += 256) {
            int row = t >> 3, ch = t & 7;
            cpa16(sb + SM_QH + row*QSTRIDE + ch*16, qh + row*128 + ch*16);
            cpa16(sb + SM_QL + row*QSTRIDE + ch*16, ql + row*128 + ch*16);
        }
    }
    // ---- prefetch i-tile 0 into buf 0 ----
    const char* khg = (const char*)(g_kTh + (size_t)n*HWSZ*CR);
    const char* klg = (const char*)(g_kTl + (size_t)n*HWSZ*CR);
    const char* vhg = (const char*)(g_vh  + (size_t)n*CR*HWSZ);
    const char* vlg = (const char*)(g_vl  + (size_t)n*CR*HWSZ);

    #define LOAD_KV(IT, BUF) do {                                                   \
        const int _i0 = (IT) * 128;                                                 \
        const uint32_t _kh = sb + SM_KH + (BUF)*128*QSTRIDE;                         \
        const uint32_t _kl = sb + SM_KL + (BUF)*128*QSTRIDE;                         \
        for (int t = tid; t < 1024; t += 256) {                                      \
            int row = t >> 3, ch = t & 7;                                            \
            cpa16(_kh + row*QSTRIDE + ch*16, khg + ((size_t)(_i0+row)*CR)*2 + ch*16);\
            cpa16(_kl + row*QSTRIDE + ch*16, klg + ((size_t)(_i0+row)*CR)*2 + ch*16);\
        }                                                                            \
        const uint32_t _vh = sb + SM_VH + (BUF)*64*VSTRIDE;                          \
        const uint32_t _vl = sb + SM_VL + (BUF)*64*VSTRIDE;                          \
        for (int t = tid; t < 1024; t += 256) {                                      \
            int c = t >> 4, ch = t & 15;                                             \
            cpa16(_vh + c*VSTRIDE + ch*16, vhg + ((size_t)c*HWSZ + _i0)*2 + ch*16);  \
            cpa16(_vl + c*VSTRIDE + ch*16, vlg + ((size_t)c*HWSZ + _i0)*2 + ch*16);  \
        }                                                                            \
    } while (0)

    LOAD_KV(0, 0);
    CPA_COMMIT();
    CPA_WAIT0();
    __syncthreads();

    // ---- persistent Q fragments: [split][kstep][4] ----
    uint32_t qf[2][4][4];
    {
        const int jrow = wid*16 + (lane & 15);
        const int coff = ((lane >> 4) << 3);     // +0 / +8 halves
        #pragma unroll
        for (int k = 0; k < 4; k++) {
            ldsm_x4(qf[0][k], sb + SM_QH + jrow*QSTRIDE + (k*16 + coff)*2);
            ldsm_x4(qf[1][k], sb + SM_QL + jrow*QSTRIDE + (k*16 + coff)*2);
        }
    }

    float accO[8][4];
    #pragma unroll
    for (int t = 0; t < 8; t++)
        #pragma unroll
        for (int r = 0; r < 4; r++) accO[t][r] = 0.f;
    float lsum = 0.f;

    const int bl_row  = lane & 7;           // ldmatrix row-within-8
    const int bl_half = (lane >> 3) & 1;    // ldmatrix k-half select

    #pragma unroll 1
    for (int it = 0; it < NITA; it++) {
        const int buf = it & 1;
        if (it + 1 < NITA) { LOAD_KV(it + 1, buf ^ 1); CPA_COMMIT(); CPA_WAIT1(); }
        else               { CPA_WAIT0(); }
        __syncthreads();

        const uint32_t khb = sb + SM_KH + buf*128*QSTRIDE;
        const uint32_t klb = sb + SM_KL + buf*128*QSTRIDE;
        const uint32_t vhb = sb + SM_VH + buf*64*VSTRIDE;
        const uint32_t vlb = sb + SM_VL + buf*64*VSTRIDE;

        #pragma unroll
        for (int ic = 0; ic < 8; ic++) {       // 16-i chunks
            // B1 fragments: K^T rows i (n dim), cols c (k dim)
            uint32_t bh[4][2][2], bl[4][2][2];
            #pragma unroll
            for (int k = 0; k < 4; k++)
                #pragma unroll
                for (int nt = 0; nt < 2; nt++) {
                    uint32_t a = (ic*16 + nt*8 + bl_row)*QSTRIDE + (k*16 + bl_half*8)*2;
                    ldsm_x2(bh[k][nt], khb + a);
                    ldsm_x2(bl[k][nt], klb + a);
                }

            float pacc[2][4];
            #pragma unroll
            for (int nt = 0; nt < 2; nt++)
                #pragma unroll
                for (int r = 0; r < 4; r++) pacc[nt][r] = 0.f;

            #pragma unroll
            for (int k = 0; k < 4; k++) {
                mma16816(pacc[0], qf[0][k], bh[k][0]);   // Qh*Kh
                mma16816(pacc[1], qf[0][k], bh[k][1]);
                mma16816(pacc[0], qf[0][k], bl[k][0]);   // Qh*Kl
                mma16816(pacc[1], qf[0][k], bl[k][1]);
                mma16816(pacc[0], qf[1][k], bh[k][0]);   // Ql*Kh
                mma16816(pacc[1], qf[1][k], bh[k][1]);
            }

            // exp (fp32) + scale + pack to A fragment for MMA2
            float e[2][4];
            #pragma unroll
            for (int nt = 0; nt < 2; nt++)
                #pragma unroll
                for (int r = 0; r < 4; r++) {
                    float v = __expf(pacc[nt][r]);
                    lsum += v;
                    e[nt][r] = v * PSCALE;
                }
            uint32_t af[4];
            af[0] = pack_h2(e[0][0], e[0][1]);
            af[1] = pack_h2(e[0][2], e[0][3]);
            af[2] = pack_h2(e[1][0], e[1][1]);
            af[3] = pack_h2(e[1][2], e[1][3]);

            // MMA2: attT[j,c] += P * V^T  (B from V rows c, cols i)
            #pragma unroll
            for (int nt2 = 0; nt2 < 8; nt2++) {
                uint32_t a = (nt2*8 + bl_row)*VSTRIDE + (ic*16 + bl_half*8)*2;
                uint32_t bv[2];
                ldsm_x2(bv, vhb + a);
                mma16816(accO[nt2], af, bv);
                ldsm_x2(bv, vlb + a);
                mma16816(accO[nt2], af, bv);
            }
        }
        __syncthreads();   // buf consumed; safe to overwrite next iter
    }

    // ---- write attT (unnormalized, rescaled) ----
    {
        int r0 = j0 + wid*16 + (lane >> 2);
        int c0 = (lane & 3) * 2;
        float* base0 = g_att + ((size_t)n*HWSZ + r0)*CR;
        float* base1 = base0 + 8*CR;
        #pragma unroll
        for (int nt2 = 0; nt2 < 8; nt2++) {
            *(float2*)&base0[nt2*8 + c0] = make_float2(accO[nt2][0]*PSCALEI, accO[nt2][1]*PSCALEI);
            *(float2*)&base1[nt2*8 + c0] = make_float2(accO[nt2][2]*PSCALEI, accO[nt2][3]*PSCALEI);
        }
    }

    // ---- deterministic block sum of exp ----
    #pragma unroll
    for (int off = 16; off > 0; off >>= 1)
        lsum += __shfl_xor_sync(0xFFFFFFFFu, lsum, off);
    if (lane == 0) ((float*)(smem + SM_RED))[wid] = lsum;
    __syncthreads();
    if (tid == 0) {
        float s = 0.f;
        #pragma unroll
        for (int w = 0; w < 8; w++) s += ((float*)(smem + SM_RED))[w];
        g_partial[n*NJT + blockIdx.x] = s;
    }
}

// ---------------------------------------------------------------------------
// Kernel 3: out[n,o,p] = g * (Watt[o,:] @ (attT[p,:]/S[n]) + batt[o]) + g
// ---------------------------------------------------------------------------
__global__ __launch_bounds__(256) void out_kernel(
    const float* __restrict__ gco,
    const float* __restrict__ Watt, const float* __restrict__ batt,
    float* __restrict__ out)
{
    __shared__ float sW[64*68];
    __shared__ float sA[64*68];
    __shared__ float sS;

    const int tid = threadIdx.x;
    const int tx = tid & 15, ty = tid >> 4;
    const int n  = blockIdx.z;
    const int o0 = blockIdx.y * 64;
    const int j0 = blockIdx.x * 64;

    if (tid == 0) {
        float s = 0.f;
        #pragma unroll
        for (int t = 0; t < NJT; t++) s += g_partial[n*NJT + t];
        sS = s;
    }
    for (int t = tid; t < 64*64; t += 256) {
        int o = t >> 6, k = t & 63;
        sW[k*68 + o] = Watt[(size_t)(o0 + o)*CR + k];
    }
    for (int t = tid; t < 64*64; t += 256) {
        int j = t >> 6, c = t & 63;
        sA[c*68 + j] = g_att[((size_t)n*HWSZ + j0 + j)*CR + c];
    }
    __syncthreads();

    float acc[4][4];
    #pragma unroll
    for (int i = 0; i < 4; i++)
        #pragma unroll
        for (int j = 0; j < 4; j++) acc[i][j] = 0.f;

    #pragma unroll 8
    for (int k = 0; k < 64; k++) {
        float4 w4 = *(float4*)&sW[k*68 + ty*4];
        float4 a4 = *(float4*)&sA[k*68 + tx*4];
        float wv[4] = {w4.x, w4.y, w4.z, w4.w};
        float av[4] = {a4.x, a4.y, a4.z, a4.w};
        #pragma unroll
        for (int i = 0; i < 4; i++)
            #pragma unroll
            for (int j = 0; j < 4; j++)
                acc[i][j] = fmaf(wv[i], av[j], acc[i][j]);
    }

    const float invS = 1.f / sS;
    #pragma unroll
    for (int oi = 0; oi < 4; oi++) {
        int o = o0 + ty*4 + oi;
        float bias = batt[o];
        size_t base = ((size_t)n*CIN + o)*HWSZ + j0 + tx*4;
        float4 g = *(const float4*)&gco[base];
        float4 r;
        r.x = g.x * (fmaf(acc[oi][0], invS, bias) + 1.f);
        r.y = g.y * (fmaf(acc[oi][1], invS, bias) + 1.f);
        r.z = g.z * (fmaf(acc[oi][2], invS, bias) + 1.f);
        r.w = g.w * (fmaf(acc[oi][3], invS, bias) + 1.f);
        *(float4*)&out[base] = r;
    }
}

// ---------------------------------------------------------------------------
extern "C" void kernel_launch(void* const* d_in, const int* in_sizes, int n_in,
                              void* d_out, int out_size)
{
    const float* x    = (const float*)d_in[0];
    const float* gco  = (const float*)d_in[1];
    const float* Wq   = (const float*)d_in[2];
    const float* bq   = (const float*)d_in[3];
    const float* Wk   = (const float*)d_in[4];
    const float* bk   = (const float*)d_in[5];
    const float* Wv   = (const float*)d_in[6];
    const float* bv   = (const float*)d_in[7];
    const float* Watt = (const float*)d_in[8];
    const float* batt = (const float*)d_in[9];
    float* out = (float*)d_out;

    cudaFuncSetAttribute(attn_kernel, cudaFuncAttributeMaxDynamicSharedMemorySize, SM_TOT);

    qkv_kernel<<<dim3(NJT, NB, 3), 256>>>(x, Wq, bq, Wk, bk, Wv, bv);
    attn_kernel<<<dim3(NJT, NB), 256, SM_TOT>>>();
    out_kernel<<<dim3(NIT, 4, NB), 256>>>(gco, Watt, batt, out);
}

// round 12
// speedup vs baseline: 3.8336x; 1.4645x over previous
#include <cuda_runtime.h>
#include <cuda_fp16.h>
#include <cstdint>

#define NB   16
#define CIN  256
#define CR   64
#define HWSZ 2304
#define NJT  18            // 2304 / 128 j tiles (attn)
#define NIT  36            // out kernel j tiles of 64
#define NITA 18            // attn i tiles of 128

#define PSCALE  4.8828125e-4f   // 2^-11 applied to exp before fp16
#define PSCALEI 2048.0f

// ---------------- scratch (device globals; no allocation allowed) ----------
__device__ __half g_xh [NB*CIN*HWSZ], g_xl [NB*CIN*HWSZ];  // x fp16 split
__device__ __half g_qTh[NB*HWSZ*CR], g_qTl[NB*HWSZ*CR];    // [n][pos][c]
__device__ __half g_kTh[NB*HWSZ*CR], g_kTl[NB*HWSZ*CR];    // [n][pos][c]
__device__ __half g_vh [NB*CR*HWSZ];                       // [n][c][pos]
__device__ float  g_att[NB*HWSZ*CR];                       // [n][pos][c]
__device__ float  g_partial[NB*NJT];

// ---------------- helpers (sm_80-level PTX only) ----------------------------
__device__ __forceinline__ uint32_t smem_u32(const void* p) {
    uint32_t a;
    asm("{ .reg .u64 t; cvta.to.shared.u64 t, %1; cvt.u32.u64 %0, t; }" : "=r"(a) : "l"(p));
    return a;
}
__device__ __forceinline__ void mma16816(float* d, const uint32_t* a, const uint32_t* b) {
    asm volatile("mma.sync.aligned.m16n8k16.row.col.f32.f16.f16.f32 "
        "{%0,%1,%2,%3}, {%4,%5,%6,%7}, {%8,%9}, {%0,%1,%2,%3};"
        : "+f"(d[0]), "+f"(d[1]), "+f"(d[2]), "+f"(d[3])
        : "r"(a[0]), "r"(a[1]), "r"(a[2]), "r"(a[3]), "r"(b[0]), "r"(b[1]));
}
__device__ __forceinline__ void ldsm_x4(uint32_t* r, uint32_t addr) {
    asm volatile("ldmatrix.sync.aligned.m8n8.x4.shared.b16 {%0,%1,%2,%3}, [%4];"
        : "=r"(r[0]), "=r"(r[1]), "=r"(r[2]), "=r"(r[3]) : "r"(addr));
}
__device__ __forceinline__ void ldsm_x4_t(uint32_t* r, uint32_t addr) {
    asm volatile("ldmatrix.sync.aligned.m8n8.x4.trans.shared.b16 {%0,%1,%2,%3}, [%4];"
        : "=r"(r[0]), "=r"(r[1]), "=r"(r[2]), "=r"(r[3]) : "r"(addr));
}
__device__ __forceinline__ void ldsm_x2(uint32_t* r, uint32_t addr) {
    asm volatile("ldmatrix.sync.aligned.m8n8.x2.shared.b16 {%0,%1}, [%2];"
        : "=r"(r[0]), "=r"(r[1]) : "r"(addr));
}
__device__ __forceinline__ void ldsm_x2_t(uint32_t* r, uint32_t addr) {
    asm volatile("ldmatrix.sync.aligned.m8n8.x2.trans.shared.b16 {%0,%1}, [%2];"
        : "=r"(r[0]), "=r"(r[1]) : "r"(addr));
}
__device__ __forceinline__ void cpa16(uint32_t dst, const void* src) {
    asm volatile("cp.async.cg.shared.global [%0], [%1], 16;" :: "r"(dst), "l"(src));
}
#define CPA_COMMIT() asm volatile("cp.async.commit_group;" ::: "memory")
#define CPA_WAIT0()  asm volatile("cp.async.wait_group 0;" ::: "memory")
#define CPA_WAIT1()  asm volatile("cp.async.wait_group 1;" ::: "memory")
__device__ __forceinline__ uint32_t pack_h2(float lo, float hi) {
    uint32_t r;
    asm("cvt.rn.f16x2.f32 %0, %1, %2;" : "=r"(r) : "f"(hi), "f"(lo));
    return r;
}

// ---------------------------------------------------------------------------
// Kernel 0: split x fp32 -> fp16 (h, l), same [n][ci][p] layout.
// ---------------------------------------------------------------------------
__global__ __launch_bounds__(256) void convert_kernel(const float* __restrict__ x)
{
    int i = (blockIdx.x * 256 + threadIdx.x) * 4;
    float4 v = *(const float4*)(x + i);
    union { __half h[4]; uint2 u; } H, L;
    float vv[4] = {v.x, v.y, v.z, v.w};
    #pragma unroll
    for (int t = 0; t < 4; t++) {
        __half hi = __float2half_rn(vv[t]);
        H.h[t] = hi;
        L.h[t] = __float2half_rn(vv[t] - __half2float(hi));
    }
    *(uint2*)&g_xh[i] = H.u;
    *(uint2*)&g_xl[i] = L.u;
}

// ---------------------------------------------------------------------------
// Kernel 1: HMMA QKV projection (fp16 3-split = fp32-class accuracy).
//  which 0/1 (q,k): C[p][c] = x^T W^T, written transposed [pos][c] h/l
//  which 2   (v)  : C[c][p] = W x,     written [c][pos] h only
// Block: 256 thr, 8 warps; tile 256 p x 64 c; K = 256 (4 kk-steps of 64).
// ---------------------------------------------------------------------------
#define XSTR 528                       // 264 halves per row (256 + pad)
#define OFF_BIAS 0
#define OFF_WH   512
#define OFF_WL   (OFF_WH + 64*XSTR)    // 34304
#define OFF_X    (OFF_WL + 64*XSTR)    // 68096; [buf:2][split:2][64*XSTR]
#define XBUF(b, s) (OFF_X + ((b)*2 + (s)) * 64*XSTR)
#define QKV_SMEM (OFF_X + 4*64*XSTR)   // 203264

__global__ __launch_bounds__(256, 1) void qkv_hmma(
    const float* __restrict__ Wq, const float* __restrict__ bq,
    const float* __restrict__ Wk, const float* __restrict__ bk,
    const float* __restrict__ Wv, const float* __restrict__ bv)
{
    extern __shared__ char sm[];
    const uint32_t sb = smem_u32(sm);
    const int tid = threadIdx.x, wid = tid >> 5, lane = tid & 31;
    const int n = blockIdx.y, p0 = blockIdx.x * 256, which = blockIdx.z;

    const float* W = (which == 0) ? Wq : (which == 1) ? Wk : Wv;
    const float* b = (which == 0) ? bq : (which == 1) ? bk : bv;

    // W fp32 -> smem fp16 h/l, bias -> smem
    if (tid < 64) ((float*)(sm + OFF_BIAS))[tid] = b[tid];
    for (int t = tid; t < 64*256; t += 256) {
        int c = t >> 8, ci = t & 255;
        float w = W[t];
        __half hi = __float2half_rn(w);
        *(__half*)(sm + OFF_WH + c*XSTR + ci*2) = hi;
        *(__half*)(sm + OFF_WL + c*XSTR + ci*2) = __float2half_rn(w - __half2float(hi));
    }

    #define LOAD_X(KK, BUF) do {                                                      \
        for (int t = tid; t < 4096; t += 256) {                                       \
            int sp = t >> 11, r = (t >> 5) & 63, ch = t & 31;                         \
            const char* src = (const char*)(sp ? g_xl : g_xh)                         \
                + ((size_t)(n*CIN + (KK)*64 + r)*HWSZ + p0)*2 + ch*16;                \
            cpa16(sb + XBUF(BUF, sp) + r*XSTR + ch*16, src);                          \
        }                                                                             \
    } while (0)

    LOAD_X(0, 0);
    CPA_COMMIT();

    float acc[16][4];      // A: [mi(2)][ni(8)] ; B: [mi(4)][ni(4)]
    #pragma unroll
    for (int t = 0; t < 16; t++)
        #pragma unroll
        for (int r = 0; r < 4; r++) acc[t][r] = 0.f;

    for (int kk = 0; kk < 4; kk++) {
        const int buf = kk & 1;
        if (kk < 3) { LOAD_X(kk + 1, buf ^ 1); CPA_COMMIT(); CPA_WAIT1(); }
        else        { CPA_WAIT0(); }
        __syncthreads();

        const uint32_t xh = sb + XBUF(buf, 0), xl = sb + XBUF(buf, 1);

        if (which < 2) {
            // ---- orientation A: A = x^T (trans ldsm), B = W ----
            #pragma unroll
            for (int k = 0; k < 4; k++) {
                const int ci = kk*64 + k*16;
                uint32_t bh[8][2], bl[8][2];
                #pragma unroll
                for (int ni = 0; ni < 8; ni++) {
                    uint32_t a = (ni*8 + (lane&7))*XSTR + (ci + ((lane>>3)&1)*8)*2;
                    ldsm_x2(bh[ni], sb + OFF_WH + a);
                    ldsm_x2(bl[ni], sb + OFF_WL + a);
                }
                #pragma unroll
                for (int mi = 0; mi < 2; mi++) {
                    uint32_t aH[4], aL[4];
                    uint32_t ar = k*16 + (lane&7) + ((lane>>4)<<3);
                    uint32_t ac = wid*32 + mi*16 + ((lane>>3)&1)*8;
                    ldsm_x4_t(aH, xh + ar*XSTR + ac*2);
                    ldsm_x4_t(aL, xl + ar*XSTR + ac*2);
                    #pragma unroll
                    for (int ni = 0; ni < 8; ni++) {
                        mma16816(acc[mi*8+ni], aH, bh[ni]);
                        mma16816(acc[mi*8+ni], aH, bl[ni]);
                        mma16816(acc[mi*8+ni], aL, bh[ni]);
                    }
                }
            }
        } else {
            // ---- orientation B: A = W, B = x^T (trans ldsm) ----
            #pragma unroll
            for (int k = 0; k < 4; k++) {
                const int ci = kk*64 + k*16;
                uint32_t bxh[4][2], bxl[4][2];
                #pragma unroll
                for (int ni = 0; ni < 4; ni++) {
                    uint32_t a = (k*16 + (lane&7) + ((lane>>3)&1)*8)*XSTR
                               + (wid*32 + ni*8)*2;
                    ldsm_x2_t(bxh[ni], xh + a);
                    ldsm_x2_t(bxl[ni], xl + a);
                }
                #pragma unroll
                for (int mi = 0; mi < 4; mi++) {
                    uint32_t aH[4], aL[4];
                    uint32_t a = (mi*16 + (lane&15))*XSTR + (ci + (lane>>4)*8)*2;
                    ldsm_x4(aH, sb + OFF_WH + a);
                    ldsm_x4(aL, sb + OFF_WL + a);
                    #pragma unroll
                    for (int ni = 0; ni < 4; ni++) {
                        mma16816(acc[mi*4+ni], aH, bxh[ni]);
                        mma16816(acc[mi*4+ni], aH, bxl[ni]);
                        mma16816(acc[mi*4+ni], aL, bxh[ni]);
                    }
                }
            }
        }
        __syncthreads();
    }

    const float* sBias = (const float*)(sm + OFF_BIAS);

    if (which < 2) {
        // epilogue A: +bias, fp16 h/l split, smem-staged coalesced store
        __half* oh = (which == 0) ? g_qTh : g_kTh;
        __half* ol = (which == 0) ? g_qTl : g_kTl;
        char* stg = sm + XBUF(0, 0) + wid*4608;   // 32 rows x 144 B, warp-private
        #pragma unroll
        for (int s = 0; s < 2; s++) {
            #pragma unroll
            for (int mi = 0; mi < 2; mi++)
                #pragma unroll
                for (int ni = 0; ni < 8; ni++) {
                    float b0 = sBias[ni*8 + (lane&3)*2];
                    float b1 = sBias[ni*8 + (lane&3)*2 + 1];
                    const float* d = acc[mi*8+ni];
                    float v0 = d[0]+b0, v1 = d[1]+b1, v2 = d[2]+b0, v3 = d[3]+b1;
                    uint32_t u0, u1;
                    if (s == 0) { u0 = pack_h2(v0, v1); u1 = pack_h2(v2, v3); }
                    else {
                        u0 = pack_h2(v0 - __half2float(__float2half_rn(v0)),
                                     v1 - __half2float(__float2half_rn(v1)));
                        u1 = pack_h2(v2 - __half2float(__float2half_rn(v2)),
                                     v3 - __half2float(__float2half_rn(v3)));
                    }
                    uint32_t cb = (ni*8 + (lane&3)*2)*2;
                    *(uint32_t*)(stg + (mi*16 + (lane>>2))*144 + cb)     = u0;
                    *(uint32_t*)(stg + (mi*16 + (lane>>2) + 8)*144 + cb) = u1;
                }
            __syncwarp();
            __half* dst = s ? ol : oh;
            #pragma unroll
            for (int i = 0; i < 8; i++) {
                int chunk = i*32 + lane, row = chunk >> 3, off = chunk & 7;
                uint4 v = *(uint4*)(stg + row*144 + off*16);
                *(uint4*)&dst[((size_t)n*HWSZ + p0 + wid*32 + row)*CR + off*8] = v;
            }
            __syncwarp();
        }
    } else {
        // epilogue B: +bias, fp16 (h only), direct half2 stores along pos
        #pragma unroll
        for (int mi = 0; mi < 4; mi++) {
            int c0 = mi*16 + (lane>>2), c1 = c0 + 8;
            float b0 = sBias[c0], b1 = sBias[c1];
            #pragma unroll
            for (int ni = 0; ni < 4; ni++) {
                const float* d = acc[mi*4+ni];
                size_t p = (size_t)p0 + wid*32 + ni*8 + (lane&3)*2;
                *(uint32_t*)&g_vh[((size_t)n*CR + c0)*HWSZ + p] = pack_h2(d[0]+b0, d[1]+b0);
                *(uint32_t*)&g_vh[((size_t)n*CR + c1)*HWSZ + p] = pack_h2(d[2]+b1, d[3]+b1);
            }
        }
    }
}

// ---------------------------------------------------------------------------
// Kernel 2: FA2-style HMMA attention.
//   MMA1: P = Q^T K (3-split) -> exp(fp32) -> fp16 * 2^-11
//   MMA2: attT += P V^T (single-fp16 V, P A-frag direct from registers)
// ---------------------------------------------------------------------------
#define QSTRIDE 144
#define VSTRIDE 272
#define SM_RED  0
#define SM_QH   128
#define SM_QL   (SM_QH + 128*QSTRIDE)
#define SM_KH   (SM_QL + 128*QSTRIDE)
#define SM_KL   (SM_KH + 2*128*QSTRIDE)
#define SM_VH   (SM_KL + 2*128*QSTRIDE)
#define SM_TOT  (SM_VH + 2*64*VSTRIDE)     // 145536

__global__ __launch_bounds__(256, 1) void attn_kernel()
{
    extern __shared__ char smem[];
    const uint32_t sb = smem_u32(smem);
    const int tid = threadIdx.x, wid = tid >> 5, lane = tid & 31;
    const int n = blockIdx.y, j0 = blockIdx.x * 128;

    {
        const char* qh = (const char*)(g_qTh + ((size_t)n*HWSZ + j0)*CR);
        const char* ql = (const char*)(g_qTl + ((size_t)n*HWSZ + j0)*CR);
        for (int t = tid; t < 1024; t += 256) {
            int row = t >> 3, ch = t & 7;
            cpa16(sb + SM_QH + row*QSTRIDE + ch*16, qh + row*128 + ch*16);
            cpa16(sb + SM_QL + row*QSTRIDE + ch*16, ql + row*128 + ch*16);
        }
    }
    const char* khg = (const char*)(g_kTh + (size_t)n*HWSZ*CR);
    const char* klg = (const char*)(g_kTl + (size_t)n*HWSZ*CR);
    const char* vhg = (const char*)(g_vh  + (size_t)n*CR*HWSZ);

    #define LOAD_KV(IT, BUF) do {                                                   \
        const int _i0 = (IT) * 128;                                                 \
        const uint32_t _kh = sb + SM_KH + (BUF)*128*QSTRIDE;                         \
        const uint32_t _kl = sb + SM_KL + (BUF)*128*QSTRIDE;                         \
        for (int t = tid; t < 1024; t += 256) {                                      \
            int row = t >> 3, ch = t & 7;                                            \
            cpa16(_kh + row*QSTRIDE + ch*16, khg + ((size_t)(_i0+row)*CR)*2 + ch*16);\
            cpa16(_kl + row*QSTRIDE + ch*16, klg + ((size_t)(_i0+row)*CR)*2 + ch*16);\
        }                                                                            \
        const uint32_t _vh = sb + SM_VH + (BUF)*64*VSTRIDE;                          \
        for (int t = tid; t < 1024; t += 256) {                                      \
            int c = t >> 4, ch = t & 15;                                             \
            cpa16(_vh + c*VSTRIDE + ch*16, vhg + ((size_t)c*HWSZ + _i0)*2 + ch*16);  \
        }                                                                            \
    } while (0)

    LOAD_KV(0, 0);
    CPA_COMMIT();
    CPA_WAIT0();
    __syncthreads();

    uint32_t qf[2][4][4];
    {
        const int jrow = wid*16 + (lane & 15);
        const int coff = ((lane >> 4) << 3);
        #pragma unroll
        for (int k = 0; k < 4; k++) {
            ldsm_x4(qf[0][k], sb + SM_QH + jrow*QSTRIDE + (k*16 + coff)*2);
            ldsm_x4(qf[1][k], sb + SM_QL + jrow*QSTRIDE + (k*16 + coff)*2);
        }
    }

    float accO[8][4];
    #pragma unroll
    for (int t = 0; t < 8; t++)
        #pragma unroll
        for (int r = 0; r < 4; r++) accO[t][r] = 0.f;
    float lsum = 0.f;

    const int bl_row  = lane & 7;
    const int bl_half = (lane >> 3) & 1;

    #pragma unroll 1
    for (int it = 0; it < NITA; it++) {
        const int buf = it & 1;
        if (it + 1 < NITA) { LOAD_KV(it + 1, buf ^ 1); CPA_COMMIT(); CPA_WAIT1(); }
        else               { CPA_WAIT0(); }
        __syncthreads();

        const uint32_t khb = sb + SM_KH + buf*128*QSTRIDE;
        const uint32_t klb = sb + SM_KL + buf*128*QSTRIDE;
        const uint32_t vhb = sb + SM_VH + buf*64*VSTRIDE;

        #pragma unroll
        for (int ic = 0; ic < 8; ic++) {
            uint32_t bh[4][2][2], bl[4][2][2];
            #pragma unroll
            for (int k = 0; k < 4; k++)
                #pragma unroll
                for (int nt = 0; nt < 2; nt++) {
                    uint32_t a = (ic*16 + nt*8 + bl_row)*QSTRIDE + (k*16 + bl_half*8)*2;
                    ldsm_x2(bh[k][nt], khb + a);
                    ldsm_x2(bl[k][nt], klb + a);
                }

            float pacc[2][4];
            #pragma unroll
            for (int nt = 0; nt < 2; nt++)
                #pragma unroll
                for (int r = 0; r < 4; r++) pacc[nt][r] = 0.f;

            #pragma unroll
            for (int k = 0; k < 4; k++) {
                mma16816(pacc[0], qf[0][k], bh[k][0]);
                mma16816(pacc[1], qf[0][k], bh[k][1]);
                mma16816(pacc[0], qf[0][k], bl[k][0]);
                mma16816(pacc[1], qf[0][k], bl[k][1]);
                mma16816(pacc[0], qf[1][k], bh[k][0]);
                mma16816(pacc[1], qf[1][k], bh[k][1]);
            }

            float e[2][4];
            #pragma unroll
            for (int nt = 0; nt < 2; nt++)
                #pragma unroll
                for (int r = 0; r < 4; r++) {
                    float v = __expf(pacc[nt][r]);
                    lsum += v;
                    e[nt][r] = v * PSCALE;
                }
            uint32_t af[4];
            af[0] = pack_h2(e[0][0], e[0][1]);
            af[1] = pack_h2(e[0][2], e[0][3]);
            af[2] = pack_h2(e[1][0], e[1][1]);
            af[3] = pack_h2(e[1][2], e[1][3]);

            #pragma unroll
            for (int nt2 = 0; nt2 < 8; nt2++) {
                uint32_t a = (nt2*8 + bl_row)*VSTRIDE + (ic*16 + bl_half*8)*2;
                uint32_t bv[2];
                ldsm_x2(bv, vhb + a);
                mma16816(accO[nt2], af, bv);
            }
        }
        __syncthreads();
    }

    {
        int r0 = j0 + wid*16 + (lane >> 2);
        int c0 = (lane & 3) * 2;
        float* base0 = g_att + ((size_t)n*HWSZ + r0)*CR;
        float* base1 = base0 + 8*CR;
        #pragma unroll
        for (int nt2 = 0; nt2 < 8; nt2++) {
            *(float2*)&base0[nt2*8 + c0] = make_float2(accO[nt2][0]*PSCALEI, accO[nt2][1]*PSCALEI);
            *(float2*)&base1[nt2*8 + c0] = make_float2(accO[nt2][2]*PSCALEI, accO[nt2][3]*PSCALEI);
        }
    }

    #pragma unroll
    for (int off = 16; off > 0; off >>= 1)
        lsum += __shfl_xor_sync(0xFFFFFFFFu, lsum, off);
    if (lane == 0) ((float*)(smem + SM_RED))[wid] = lsum;
    __syncthreads();
    if (tid == 0) {
        float s = 0.f;
        #pragma unroll
        for (int w = 0; w < 8; w++) s += ((float*)(smem + SM_RED))[w];
        g_partial[n*NJT + blockIdx.x] = s;
    }
}

// ---------------------------------------------------------------------------
// Kernel 3: out[n,o,p] = g * (Watt[o,:] @ (attT[p,:]/S[n]) + batt[o]) + g
// ---------------------------------------------------------------------------
__global__ __launch_bounds__(256) void out_kernel(
    const float* __restrict__ gco,
    const float* __restrict__ Watt, const float* __restrict__ batt,
    float* __restrict__ out)
{
    __shared__ float sW[64*68];
    __shared__ float sA[64*68];
    __shared__ float sS;

    const int tid = threadIdx.x;
    const int tx = tid & 15, ty = tid >> 4;
    const int n  = blockIdx.z;
    const int o0 = blockIdx.y * 64;
    const int j0 = blockIdx.x * 64;

    if (tid == 0) {
        float s = 0.f;
        #pragma unroll
        for (int t = 0; t < NJT; t++) s += g_partial[n*NJT + t];
        sS = s;
    }
    for (int t = tid; t < 64*64; t += 256) {
        int o = t >> 6, k = t & 63;
        sW[k*68 + o] = Watt[(size_t)(o0 + o)*CR + k];
    }
    for (int t = tid; t < 64*64; t += 256) {
        int j = t >> 6, c = t & 63;
        sA[c*68 + j] = g_att[((size_t)n*HWSZ + j0 + j)*CR + c];
    }
    __syncthreads();

    float acc[4][4];
    #pragma unroll
    for (int i = 0; i < 4; i++)
        #pragma unroll
        for (int j = 0; j < 4; j++) acc[i][j] = 0.f;

    #pragma unroll 8
    for (int k = 0; k < 64; k++) {
        float4 w4 = *(float4*)&sW[k*68 + ty*4];
        float4 a4 = *(float4*)&sA[k*68 + tx*4];
        float wv[4] = {w4.x, w4.y, w4.z, w4.w};
        float av[4] = {a4.x, a4.y, a4.z, a4.w};
        #pragma unroll
        for (int i = 0; i < 4; i++)
            #pragma unroll
            for (int j = 0; j < 4; j++)
                acc[i][j] = fmaf(wv[i], av[j], acc[i][j]);
    }

    const float invS = 1.f / sS;
    #pragma unroll
    for (int oi = 0; oi < 4; oi++) {
        int o = o0 + ty*4 + oi;
        float bias = batt[o];
        size_t base = ((size_t)n*CIN + o)*HWSZ + j0 + tx*4;
        float4 g = *(const float4*)&gco[base];
        float4 r;
        r.x = g.x * (fmaf(acc[oi][0], invS, bias) + 1.f);
        r.y = g.y * (fmaf(acc[oi][1], invS, bias) + 1.f);
        r.z = g.z * (fmaf(acc[oi][2], invS, bias) + 1.f);
        r.w = g.w * (fmaf(acc[oi][3], invS, bias) + 1.f);
        *(float4*)&out[base] = r;
    }
}

// ---------------------------------------------------------------------------
extern "C" void kernel_launch(void* const* d_in, const int* in_sizes, int n_in,
                              void* d_out, int out_size)
{
    const float* x    = (const float*)d_in[0];
    const float* gco  = (const float*)d_in[1];
    const float* Wq   = (const float*)d_in[2];
    const float* bq   = (const float*)d_in[3];
    const float* Wk   = (const float*)d_in[4];
    const float* bk   = (const float*)d_in[5];
    const float* Wv   = (const float*)d_in[6];
    const float* bv   = (const float*)d_in[7];
    const float* Watt = (const float*)d_in[8];
    const float* batt = (const float*)d_in[9];
    float* out = (float*)d_out;

    cudaFuncSetAttribute(qkv_hmma,  cudaFuncAttributeMaxDynamicSharedMemorySize, QKV_SMEM);
    cudaFuncSetAttribute(attn_kernel, cudaFuncAttributeMaxDynamicSharedMemorySize, SM_TOT);

    convert_kernel<<<NB*CIN*HWSZ/1024, 256>>>(x);
    qkv_hmma<<<dim3(9, NB, 3), 256, QKV_SMEM>>>(Wq, bq, Wk, bk, Wv, bv);
    attn_kernel<<<dim3(NJT, NB), 256, SM_TOT>>>();
    out_kernel<<<dim3(NIT, 4, NB), 256>>>(gco, Watt, batt, out);
}

// round 13
// speedup vs baseline: 6.6396x; 1.7319x over previous
#include <cuda_runtime.h>
#include <cuda_fp16.h>
#include <cstdint>

#define NB   16
#define CIN  256
#define CR   64
#define HWSZ 2304
#define NJT  18            // 2304 / 128 j tiles (attn)
#define NITA 18            // attn i tiles of 128

#define PSCALE  4.8828125e-4f   // 2^-11 applied to exp before fp16
#define ASCALE  0.0625f         // extra 2^-4 when storing att fp16
// normalizer in out kernel: 2^15 / S

// ---------------- scratch (device globals; no allocation allowed) ----------
__device__ __half g_xh [NB*CIN*HWSZ];                      // x fp16
__device__ __half g_qT [NB*HWSZ*CR];                       // [n][pos][c]
__device__ __half g_kT [NB*HWSZ*CR];                       // [n][pos][c]
__device__ __half g_vh [NB*CR*HWSZ];                       // [n][c][pos]
__device__ __half g_attF[NB*HWSZ*CR];                      // [n][pos][c], x2^-15
__device__ float  g_partial[NB*NJT];

// ---------------- helpers (sm_80-level PTX only) ----------------------------
__device__ __forceinline__ uint32_t smem_u32(const void* p) {
    uint32_t a;
    asm("{ .reg .u64 t; cvta.to.shared.u64 t, %1; cvt.u32.u64 %0, t; }" : "=r"(a) : "l"(p));
    return a;
}
__device__ __forceinline__ void mma16816(float* d, const uint32_t* a, const uint32_t* b) {
    asm volatile("mma.sync.aligned.m16n8k16.row.col.f32.f16.f16.f32 "
        "{%0,%1,%2,%3}, {%4,%5,%6,%7}, {%8,%9}, {%0,%1,%2,%3};"
        : "+f"(d[0]), "+f"(d[1]), "+f"(d[2]), "+f"(d[3])
        : "r"(a[0]), "r"(a[1]), "r"(a[2]), "r"(a[3]), "r"(b[0]), "r"(b[1]));
}
__device__ __forceinline__ void ldsm_x4(uint32_t* r, uint32_t addr) {
    asm volatile("ldmatrix.sync.aligned.m8n8.x4.shared.b16 {%0,%1,%2,%3}, [%4];"
        : "=r"(r[0]), "=r"(r[1]), "=r"(r[2]), "=r"(r[3]) : "r"(addr));
}
__device__ __forceinline__ void ldsm_x4_t(uint32_t* r, uint32_t addr) {
    asm volatile("ldmatrix.sync.aligned.m8n8.x4.trans.shared.b16 {%0,%1,%2,%3}, [%4];"
        : "=r"(r[0]), "=r"(r[1]), "=r"(r[2]), "=r"(r[3]) : "r"(addr));
}
__device__ __forceinline__ void ldsm_x2(uint32_t* r, uint32_t addr) {
    asm volatile("ldmatrix.sync.aligned.m8n8.x2.shared.b16 {%0,%1}, [%2];"
        : "=r"(r[0]), "=r"(r[1]) : "r"(addr));
}
__device__ __forceinline__ void ldsm_x2_t(uint32_t* r, uint32_t addr) {
    asm volatile("ldmatrix.sync.aligned.m8n8.x2.trans.shared.b16 {%0,%1}, [%2];"
        : "=r"(r[0]), "=r"(r[1]) : "r"(addr));
}
__device__ __forceinline__ void cpa16(uint32_t dst, const void* src) {
    asm volatile("cp.async.cg.shared.global [%0], [%1], 16;" :: "r"(dst), "l"(src));
}
#define CPA_COMMIT() asm volatile("cp.async.commit_group;" ::: "memory")
#define CPA_WAIT0()  asm volatile("cp.async.wait_group 0;" ::: "memory")
#define CPA_WAIT1()  asm volatile("cp.async.wait_group 1;" ::: "memory")
__device__ __forceinline__ uint32_t pack_h2(float lo, float hi) {
    uint32_t r;
    asm("cvt.rn.f16x2.f32 %0, %1, %2;" : "=r"(r) : "f"(hi), "f"(lo));
    return r;
}

// ---------------------------------------------------------------------------
// Kernel 0: x fp32 -> fp16, same [n][ci][p] layout. 8 elems/thread.
// ---------------------------------------------------------------------------
__global__ __launch_bounds__(256) void convert_kernel(const float* __restrict__ x)
{
    size_t i = ((size_t)blockIdx.x * 256 + threadIdx.x) * 8;
    float4 v0 = *(const float4*)(x + i);
    float4 v1 = *(const float4*)(x + i + 4);
    uint4 o;
    o.x = pack_h2(v0.x, v0.y);
    o.y = pack_h2(v0.z, v0.w);
    o.z = pack_h2(v1.x, v1.y);
    o.w = pack_h2(v1.z, v1.w);
    *(uint4*)&g_xh[i] = o;
}

// ---------------------------------------------------------------------------
// Kernel 1: HMMA QKV projection (single fp16).
//  which 0/1 (q,k): C[p][c] = x^T W^T, written transposed [pos][c]
//  which 2   (v)  : C[c][p] = W x,     written [c][pos]
// Block: 256 thr, 8 warps; tile 256 p x 64 c; K = 256 (4 kk-steps of 64).
// ---------------------------------------------------------------------------
#define XSTR 528                       // 264 halves per row (256 + pad)
#define OFF_BIAS 0
#define OFF_WH   512
#define OFF_X    (OFF_WH + 64*XSTR)    // 34304; [buf:2][64*XSTR]
#define XBUF(b)  (OFF_X + (b) * 64*XSTR)
#define QKV_SMEM (OFF_X + 2*64*XSTR)   // 101888

__global__ __launch_bounds__(256, 1) void qkv_hmma(
    const float* __restrict__ Wq, const float* __restrict__ bq,
    const float* __restrict__ Wk, const float* __restrict__ bk,
    const float* __restrict__ Wv, const float* __restrict__ bv)
{
    extern __shared__ char sm[];
    const uint32_t sb = smem_u32(sm);
    const int tid = threadIdx.x, wid = tid >> 5, lane = tid & 31;
    const int n = blockIdx.y, p0 = blockIdx.x * 256, which = blockIdx.z;

    const float* W = (which == 0) ? Wq : (which == 1) ? Wk : Wv;
    const float* b = (which == 0) ? bq : (which == 1) ? bk : bv;

    if (tid < 64) ((float*)(sm + OFF_BIAS))[tid] = b[tid];
    for (int t = tid; t < 64*256; t += 256) {
        int c = t >> 8, ci = t & 255;
        *(__half*)(sm + OFF_WH + c*XSTR + ci*2) = __float2half_rn(W[t]);
    }

    #define LOAD_X(KK, BUF) do {                                                      \
        for (int t = tid; t < 2048; t += 256) {                                       \
            int r = t >> 5, ch = t & 31;                                              \
            const char* src = (const char*)g_xh                                       \
                + ((size_t)(n*CIN + (KK)*64 + r)*HWSZ + p0)*2 + ch*16;                \
            cpa16(sb + XBUF(BUF) + r*XSTR + ch*16, src);                              \
        }                                                                             \
    } while (0)

    LOAD_X(0, 0);
    CPA_COMMIT();

    float acc[16][4];      // A: [mi(2)][ni(8)] ; B: [mi(4)][ni(4)]
    #pragma unroll
    for (int t = 0; t < 16; t++)
        #pragma unroll
        for (int r = 0; r < 4; r++) acc[t][r] = 0.f;

    for (int kk = 0; kk < 4; kk++) {
        const int buf = kk & 1;
        if (kk < 3) { LOAD_X(kk + 1, buf ^ 1); CPA_COMMIT(); CPA_WAIT1(); }
        else        { CPA_WAIT0(); }
        __syncthreads();

        const uint32_t xh = sb + XBUF(buf);

        if (which < 2) {
            // ---- orientation A: A = x^T (trans ldsm), B = W ----
            #pragma unroll
            for (int k = 0; k < 4; k++) {
                const int ci = kk*64 + k*16;
                uint32_t bh[8][2];
                #pragma unroll
                for (int ni = 0; ni < 8; ni++) {
                    uint32_t a = (ni*8 + (lane&7))*XSTR + (ci + ((lane>>3)&1)*8)*2;
                    ldsm_x2(bh[ni], sb + OFF_WH + a);
                }
                #pragma unroll
                for (int mi = 0; mi < 2; mi++) {
                    uint32_t aH[4];
                    uint32_t ar = k*16 + (lane&7) + ((lane>>4)<<3);
                    uint32_t ac = wid*32 + mi*16 + ((lane>>3)&1)*8;
                    ldsm_x4_t(aH, xh + ar*XSTR + ac*2);
                    #pragma unroll
                    for (int ni = 0; ni < 8; ni++)
                        mma16816(acc[mi*8+ni], aH, bh[ni]);
                }
            }
        } else {
            // ---- orientation B: A = W, B = x^T (trans ldsm) ----
            #pragma unroll
            for (int k = 0; k < 4; k++) {
                const int ci = kk*64 + k*16;
                uint32_t bxh[4][2];
                #pragma unroll
                for (int ni = 0; ni < 4; ni++) {
                    uint32_t a = (k*16 + (lane&7) + ((lane>>3)&1)*8)*XSTR
                               + (wid*32 + ni*8)*2;
                    ldsm_x2_t(bxh[ni], xh + a);
                }
                #pragma unroll
                for (int mi = 0; mi < 4; mi++) {
                    uint32_t aH[4];
                    uint32_t a = (mi*16 + (lane&15))*XSTR + (ci + (lane>>4)*8)*2;
                    ldsm_x4(aH, sb + OFF_WH + a);
                    #pragma unroll
                    for (int ni = 0; ni < 4; ni++)
                        mma16816(acc[mi*4+ni], aH, bxh[ni]);
                }
            }
        }
        __syncthreads();
    }

    const float* sBias = (const float*)(sm + OFF_BIAS);

    if (which < 2) {
        // epilogue A: +bias, fp16, smem-staged coalesced store
        __half* oh = (which == 0) ? g_qT : g_kT;
        char* stg = sm + XBUF(0) + wid*4608;   // 32 rows x 144 B, warp-private
        #pragma unroll
        for (int mi = 0; mi < 2; mi++)
            #pragma unroll
            for (int ni = 0; ni < 8; ni++) {
                float b0 = sBias[ni*8 + (lane&3)*2];
                float b1 = sBias[ni*8 + (lane&3)*2 + 1];
                const float* d = acc[mi*8+ni];
                uint32_t u0 = pack_h2(d[0]+b0, d[1]+b1);
                uint32_t u1 = pack_h2(d[2]+b0, d[3]+b1);
                uint32_t cb = (ni*8 + (lane&3)*2)*2;
                *(uint32_t*)(stg + (mi*16 + (lane>>2))*144 + cb)     = u0;
                *(uint32_t*)(stg + (mi*16 + (lane>>2) + 8)*144 + cb) = u1;
            }
        __syncwarp();
        #pragma unroll
        for (int i = 0; i < 8; i++) {
            int chunk = i*32 + lane, row = chunk >> 3, off = chunk & 7;
            uint4 v = *(uint4*)(stg + row*144 + off*16);
            *(uint4*)&oh[((size_t)n*HWSZ + p0 + wid*32 + row)*CR + off*8] = v;
        }
    } else {
        // epilogue B: +bias, fp16, direct half2 stores along pos
        #pragma unroll
        for (int mi = 0; mi < 4; mi++) {
            int c0 = mi*16 + (lane>>2), c1 = c0 + 8;
            float b0 = sBias[c0], b1 = sBias[c1];
            #pragma unroll
            for (int ni = 0; ni < 4; ni++) {
                const float* d = acc[mi*4+ni];
                size_t p = (size_t)p0 + wid*32 + ni*8 + (lane&3)*2;
                *(uint32_t*)&g_vh[((size_t)n*CR + c0)*HWSZ + p] = pack_h2(d[0]+b0, d[1]+b0);
                *(uint32_t*)&g_vh[((size_t)n*CR + c1)*HWSZ + p] = pack_h2(d[2]+b1, d[3]+b1);
            }
        }
    }
}

// ---------------------------------------------------------------------------
// Kernel 2: FA2-style HMMA attention (single fp16).
//   MMA1: P = Q^T K -> exp(fp32) -> fp16 * 2^-11
//   MMA2: attT += P V^T  (P A-frag direct from registers)
// 2 CTAs/SM (90 KB smem each).
// ---------------------------------------------------------------------------
#define QSTRIDE 144
#define VSTRIDE 272
#define SM_RED  0
#define SM_QH   128
#define SM_KH   (SM_QH + 128*QSTRIDE)            // 18560, 2 bufs
#define SM_VH   (SM_KH + 2*128*QSTRIDE)          // 55424, 2 bufs
#define SM_TOT  (SM_VH + 2*64*VSTRIDE)           // 90240

__global__ __launch_bounds__(256, 2) void attn_kernel()
{
    extern __shared__ char smem[];
    const uint32_t sb = smem_u32(smem);
    const int tid = threadIdx.x, wid = tid >> 5, lane = tid & 31;
    const int n = blockIdx.y, j0 = blockIdx.x * 128;

    {
        const char* qh = (const char*)(g_qT + ((size_t)n*HWSZ + j0)*CR);
        for (int t = tid; t < 1024; t += 256) {
            int row = t >> 3, ch = t & 7;
            cpa16(sb + SM_QH + row*QSTRIDE + ch*16, qh + row*128 + ch*16);
        }
    }
    const char* khg = (const char*)(g_kT + (size_t)n*HWSZ*CR);
    const char* vhg = (const char*)(g_vh + (size_t)n*CR*HWSZ);

    #define LOAD_KV(IT, BUF) do {                                                   \
        const int _i0 = (IT) * 128;                                                 \
        const uint32_t _kh = sb + SM_KH + (BUF)*128*QSTRIDE;                         \
        for (int t = tid; t < 1024; t += 256) {                                      \
            int row = t >> 3, ch = t & 7;                                            \
            cpa16(_kh + row*QSTRIDE + ch*16, khg + ((size_t)(_i0+row)*CR)*2 + ch*16);\
        }                                                                            \
        const uint32_t _vh = sb + SM_VH + (BUF)*64*VSTRIDE;                          \
        for (int t = tid; t < 1024; t += 256) {                                      \
            int c = t >> 4, ch = t & 15;                                             \
            cpa16(_vh + c*VSTRIDE + ch*16, vhg + ((size_t)c*HWSZ + _i0)*2 + ch*16);  \
        }                                                                            \
    } while (0)

    LOAD_KV(0, 0);
    CPA_COMMIT();
    CPA_WAIT0();
    __syncthreads();

    uint32_t qf[4][4];
    {
        const int jrow = wid*16 + (lane & 15);
        const int coff = ((lane >> 4) << 3);
        #pragma unroll
        for (int k = 0; k < 4; k++)
            ldsm_x4(qf[k], sb + SM_QH + jrow*QSTRIDE + (k*16 + coff)*2);
    }

    float accO[8][4];
    #pragma unroll
    for (int t = 0; t < 8; t++)
        #pragma unroll
        for (int r = 0; r < 4; r++) accO[t][r] = 0.f;
    float lsum = 0.f;

    const int bl_row  = lane & 7;
    const int bl_half = (lane >> 3) & 1;

    #pragma unroll 1
    for (int it = 0; it < NITA; it++) {
        const int buf = it & 1;
        if (it + 1 < NITA) { LOAD_KV(it + 1, buf ^ 1); CPA_COMMIT(); CPA_WAIT1(); }
        else               { CPA_WAIT0(); }
        __syncthreads();

        const uint32_t khb = sb + SM_KH + buf*128*QSTRIDE;
        const uint32_t vhb = sb + SM_VH + buf*64*VSTRIDE;

        #pragma unroll
        for (int ic = 0; ic < 8; ic++) {
            uint32_t bh[4][2][2];
            #pragma unroll
            for (int k = 0; k < 4; k++)
                #pragma unroll
                for (int nt = 0; nt < 2; nt++) {
                    uint32_t a = (ic*16 + nt*8 + bl_row)*QSTRIDE + (k*16 + bl_half*8)*2;
                    ldsm_x2(bh[k][nt], khb + a);
                }

            float pacc[2][4];
            #pragma unroll
            for (int nt = 0; nt < 2; nt++)
                #pragma unroll
                for (int r = 0; r < 4; r++) pacc[nt][r] = 0.f;

            #pragma unroll
            for (int k = 0; k < 4; k++) {
                mma16816(pacc[0], qf[k], bh[k][0]);
                mma16816(pacc[1], qf[k], bh[k][1]);
            }

            float e[2][4];
            #pragma unroll
            for (int nt = 0; nt < 2; nt++)
                #pragma unroll
                for (int r = 0; r < 4; r++) {
                    float v = __expf(pacc[nt][r]);
                    lsum += v;
                    e[nt][r] = v * PSCALE;
                }
            uint32_t af[4];
            af[0] = pack_h2(e[0][0], e[0][1]);
            af[1] = pack_h2(e[0][2], e[0][3]);
            af[2] = pack_h2(e[1][0], e[1][1]);
            af[3] = pack_h2(e[1][2], e[1][3]);

            #pragma unroll
            for (int nt2 = 0; nt2 < 8; nt2++) {
                uint32_t a = (nt2*8 + bl_row)*VSTRIDE + (ic*16 + bl_half*8)*2;
                uint32_t bv[2];
                ldsm_x2(bv, vhb + a);
                mma16816(accO[nt2], af, bv);
            }
        }
        __syncthreads();
    }

    // write attT as fp16 (scale x2^-4 on top of P's 2^-11)
    {
        int r0 = j0 + wid*16 + (lane >> 2);
        int c0 = (lane & 3) * 2;
        __half* base0 = g_attF + ((size_t)n*HWSZ + r0)*CR;
        __half* base1 = base0 + 8*CR;
        #pragma unroll
        for (int nt2 = 0; nt2 < 8; nt2++) {
            *(uint32_t*)&base0[nt2*8 + c0] = pack_h2(accO[nt2][0]*ASCALE, accO[nt2][1]*ASCALE);
            *(uint32_t*)&base1[nt2*8 + c0] = pack_h2(accO[nt2][2]*ASCALE, accO[nt2][3]*ASCALE);
        }
    }

    #pragma unroll
    for (int off = 16; off > 0; off >>= 1)
        lsum += __shfl_xor_sync(0xFFFFFFFFu, lsum, off);
    if (lane == 0) ((float*)(smem + SM_RED))[wid] = lsum;
    __syncthreads();
    if (tid == 0) {
        float s = 0.f;
        #pragma unroll
        for (int w = 0; w < 8; w++) s += ((float*)(smem + SM_RED))[w];
        g_partial[n*NJT + blockIdx.x] = s;
    }
}

// ---------------------------------------------------------------------------
// Kernel 3: HMMA output conv + normalize + residual.
// out[o][p] = gco * (Watt@attF * 2^15/S + batt + 1)
// Block tile: 128 o x 128 p, K=64. Grid (18 p, 2 o, 16 n).
// ---------------------------------------------------------------------------
#define OW_STR 144
#define OST_STR 160
#define OO_W   128
#define OO_A   (OO_W + 128*OW_STR)        // 18560
#define OO_ST  (OO_A + 128*OW_STR)        // 36992; per-warp 64x(160B)
#define OUT_SMEM (OO_ST + 8*64*OST_STR)   // 118912

__global__ __launch_bounds__(256, 1) void out_hmma(
    const float* __restrict__ gco,
    const float* __restrict__ Watt, const float* __restrict__ batt,
    float* __restrict__ out)
{
    extern __shared__ char sm[];
    const uint32_t sb = smem_u32(sm);
    const int tid = threadIdx.x, wid = tid >> 5, lane = tid & 31;
    const int n = blockIdx.z, o0 = blockIdx.y * 128, p0 = blockIdx.x * 128;

    if (tid == 0) {
        float s = 0.f;
        #pragma unroll
        for (int t = 0; t < NJT; t++) s += g_partial[n*NJT + t];
        *(float*)sm = 32768.0f / s;
    }
    // Watt fp32 -> fp16 smem [o][c]
    for (int t = tid; t < 128*64; t += 256) {
        int o = t >> 6, c = t & 63;
        *(__half*)(sm + OO_W + o*OW_STR + c*2) =
            __float2half_rn(Watt[(size_t)(o0 + o)*CR + c]);
    }
    // att fp16 -> smem [p][c]
    {
        const char* ag = (const char*)(g_attF + ((size_t)n*HWSZ + p0)*CR);
        for (int t = tid; t < 1024; t += 256) {
            int r = t >> 3, ch = t & 7;
            cpa16(sb + OO_A + r*OW_STR + ch*16, ag + r*128 + ch*16);
        }
    }
    CPA_COMMIT();
    CPA_WAIT0();
    __syncthreads();

    const int wo = wid & 1, wp = wid >> 1;
    float acc[16][4];
    #pragma unroll
    for (int t = 0; t < 16; t++)
        #pragma unroll
        for (int r = 0; r < 4; r++) acc[t][r] = 0.f;

    #pragma unroll
    for (int k = 0; k < 4; k++) {
        uint32_t bA[4][2];
        #pragma unroll
        for (int ni = 0; ni < 4; ni++)
            ldsm_x2(bA[ni], sb + OO_A + (wp*32 + ni*8 + (lane&7))*OW_STR
                                      + (k*16 + ((lane>>3)&1)*8)*2);
        #pragma unroll
        for (int mi = 0; mi < 4; mi++) {
            uint32_t aW[4];
            ldsm_x4(aW, sb + OO_W + (wo*64 + mi*16 + (lane&15))*OW_STR
                                  + (k*16 + ((lane>>4)<<3))*2);
            #pragma unroll
            for (int ni = 0; ni < 4; ni++)
                mma16816(acc[mi*4+ni], aW, bA[ni]);
        }
    }

    const float oscale = *(const float*)sm;

    // stage per-warp 64o x 32p fp32 tile
    char* stg = sm + OO_ST + wid*(64*OST_STR);
    #pragma unroll
    for (int mi = 0; mi < 4; mi++)
        #pragma unroll
        for (int ni = 0; ni < 4; ni++) {
            int r = mi*16 + (lane>>2), c = ni*8 + (lane&3)*2;
            const float* d = acc[mi*4+ni];
            *(float2*)(stg + r*OST_STR + c*4)       = make_float2(d[0], d[1]);
            *(float2*)(stg + (r+8)*OST_STR + c*4)   = make_float2(d[2], d[3]);
        }
    __syncwarp();

    // fused epilogue: coalesced float4 gco read / out write
    #pragma unroll
    for (int i = 0; i < 16; i++) {
        int r = i*4 + (lane >> 3);            // local o row 0..63
        int o = o0 + wo*64 + r;
        int pc = (lane & 7) * 4;              // local p col
        float4 a = *(float4*)(stg + r*OST_STR + pc*4);
        float bias = batt[o] + 1.f;
        size_t gbase = ((size_t)n*CIN + o)*HWSZ + p0 + wp*32 + pc;
        float4 g = *(const float4*)&gco[gbase];
        float4 rr;
        rr.x = g.x * fmaf(a.x, oscale, bias);
        rr.y = g.y * fmaf(a.y, oscale, bias);
        rr.z = g.z * fmaf(a.z, oscale, bias);
        rr.w = g.w * fmaf(a.w, oscale, bias);
        *(float4*)&out[gbase] = rr;
    }
}

// ---------------------------------------------------------------------------
extern "C" void kernel_launch(void* const* d_in, const int* in_sizes, int n_in,
                              void* d_out, int out_size)
{
    const float* x    = (const float*)d_in[0];
    const float* gco  = (const float*)d_in[1];
    const float* Wq   = (const float*)d_in[2];
    const float* bq   = (const float*)d_in[3];
    const float* Wk   = (const float*)d_in[4];
    const float* bk   = (const float*)d_in[5];
    const float* Wv   = (const float*)d_in[6];
    const float* bv   = (const float*)d_in[7];
    const float* Watt = (const float*)d_in[8];
    const float* batt = (const float*)d_in[9];
    float* out = (float*)d_out;

    cudaFuncSetAttribute(qkv_hmma,    cudaFuncAttributeMaxDynamicSharedMemorySize, QKV_SMEM);
    cudaFuncSetAttribute(attn_kernel, cudaFuncAttributeMaxDynamicSharedMemorySize, SM_TOT);
    cudaFuncSetAttribute(out_hmma,    cudaFuncAttributeMaxDynamicSharedMemorySize, OUT_SMEM);

    convert_kernel<<<NB*CIN*HWSZ/2048, 256>>>(x);
    qkv_hmma<<<dim3(9, NB, 3), 256, QKV_SMEM>>>(Wq, bq, Wk, bk, Wv, bv);
    attn_kernel<<<dim3(NJT, NB), 256, SM_TOT>>>();
    out_hmma<<<dim3(18, 2, NB), 256, OUT_SMEM>>>(gco, Watt, batt, out);
}